// round 1
// baseline (speedup 1.0000x reference)
#include <cuda_runtime.h>
#include <cuda_bf16.h>

#define N_USERS 100000
#define N_ITEMS 200000
#define N_NODES (N_USERS + N_ITEMS)
#define NNZ     9600000
#define DIM     64
#define TOTAL   ((size_t)N_NODES * DIM)
#define TOTAL4  (TOTAL / 4)

// Double-buffered layer embeddings (alloc-free rule: __device__ globals).
__device__ __align__(16) float g_emb0[TOTAL];
__device__ __align__(16) float g_emb1[TOTAL];

// ---------------------------------------------------------------------------
// init: emb0 = concat(user, item); out(acc) = same; emb1 = 0 (fresh each call
// so graph replay is deterministic).
// ---------------------------------------------------------------------------
__global__ __launch_bounds__(256) void init_kernel(
    const float* __restrict__ user_emb,
    const float* __restrict__ item_emb,
    float* __restrict__ out)
{
    size_t i = (size_t)blockIdx.x * blockDim.x + threadIdx.x;
    if (i >= TOTAL4) return;
    const size_t ub = (size_t)N_USERS * DIM / 4;
    float4 v = (i < ub) ? ((const float4*)user_emb)[i]
                        : ((const float4*)item_emb)[i - ub];
    ((float4*)g_emb0)[i] = v;
    ((float4*)out)[i]    = v;
    ((float4*)g_emb1)[i] = make_float4(0.f, 0.f, 0.f, 0.f);
}

// ---------------------------------------------------------------------------
// SpMM scatter: 16 threads per edge, one float4 per thread.
// dst must be pre-zeroed. Uses red.global.add.v4.f32 (fire-and-forget,
// 16B granularity -> 4x fewer L2 atomic ops than scalar atomicAdd).
// ---------------------------------------------------------------------------
__global__ __launch_bounds__(256) void spmm_kernel(
    const int*   __restrict__ rows,
    const int*   __restrict__ cols,
    const float* __restrict__ vals,
    const float* __restrict__ src,
    float*       __restrict__ dst)
{
    long long t = (long long)blockIdx.x * blockDim.x + threadIdx.x;
    long long e = t >> 4;
    if (e >= NNZ) return;
    int sub = (int)(t & 15);

    int   r = __ldg(rows + e);
    int   c = __ldg(cols + e);
    float v = __ldg(vals + e);

    float4 x = *(const float4*)(src + (size_t)c * DIM + sub * 4);
    float* p = dst + (size_t)r * DIM + sub * 4;
    asm volatile("red.global.add.v4.f32 [%0], {%1,%2,%3,%4};"
                 :: "l"(p),
                    "f"(x.x * v), "f"(x.y * v), "f"(x.z * v), "f"(x.w * v)
                 : "memory");
}

// ---------------------------------------------------------------------------
// acc += layer; zero the other buffer for the NEXT layer's scatter.
// ---------------------------------------------------------------------------
__global__ __launch_bounds__(256) void accum_kernel(
    const float* __restrict__ layer,
    float*       __restrict__ acc,
    float*       __restrict__ zbuf)
{
    size_t i = (size_t)blockIdx.x * blockDim.x + threadIdx.x;
    if (i >= TOTAL4) return;
    float4 a = ((float4*)acc)[i];
    float4 l = ((const float4*)layer)[i];
    a.x += l.x; a.y += l.y; a.z += l.z; a.w += l.w;
    ((float4*)acc)[i]  = a;
    ((float4*)zbuf)[i] = make_float4(0.f, 0.f, 0.f, 0.f);
}

// Final layer: out = (acc + layer) * 0.25
__global__ __launch_bounds__(256) void accum_final_kernel(
    const float* __restrict__ layer,
    float*       __restrict__ acc)
{
    size_t i = (size_t)blockIdx.x * blockDim.x + threadIdx.x;
    if (i >= TOTAL4) return;
    float4 a = ((float4*)acc)[i];
    float4 l = ((const float4*)layer)[i];
    a.x = (a.x + l.x) * 0.25f;
    a.y = (a.y + l.y) * 0.25f;
    a.z = (a.z + l.z) * 0.25f;
    a.w = (a.w + l.w) * 0.25f;
    ((float4*)acc)[i] = a;
}

extern "C" void kernel_launch(void* const* d_in, const int* in_sizes, int n_in,
                              void* d_out, int out_size)
{
    const int*   rows     = (const int*)  d_in[0];
    const int*   cols     = (const int*)  d_in[1];
    const float* vals     = (const float*)d_in[2];
    const float* user_emb = (const float*)d_in[3];
    const float* item_emb = (const float*)d_in[4];
    float*       out      = (float*)d_out;

    float *e0, *e1;
    cudaGetSymbolAddress((void**)&e0, g_emb0);
    cudaGetSymbolAddress((void**)&e1, g_emb1);

    const int ew_threads = 256;
    const long long spmm_threads = (long long)NNZ * 16;
    const int spmm_blocks = (int)((spmm_threads + ew_threads - 1) / ew_threads);
    const int vec_blocks  = (int)((TOTAL4 + ew_threads - 1) / ew_threads);

    // init: emb0 = input, acc(out) = input, emb1 = 0
    init_kernel<<<vec_blocks, ew_threads>>>(user_emb, item_emb, out);

    // Layer 0: emb0 -> emb1 ; acc += emb1 ; emb0 = 0
    spmm_kernel<<<spmm_blocks, ew_threads>>>(rows, cols, vals, e0, e1);
    accum_kernel<<<vec_blocks, ew_threads>>>(e1, out, e0);

    // Layer 1: emb1 -> emb0 ; acc += emb0 ; emb1 = 0
    spmm_kernel<<<spmm_blocks, ew_threads>>>(rows, cols, vals, e1, e0);
    accum_kernel<<<vec_blocks, ew_threads>>>(e0, out, e1);

    // Layer 2: emb0 -> emb1 ; out = (acc + emb1) / 4
    spmm_kernel<<<spmm_blocks, ew_threads>>>(rows, cols, vals, e0, e1);
    accum_final_kernel<<<vec_blocks, ew_threads>>>(e1, out);
}